// round 14
// baseline (speedup 1.0000x reference)
#include <cuda_runtime.h>
#include <cuda_bf16.h>
#include <cstdint>
#include <cstddef>

#define NN 50000
#define FD 128
#define NE 600000
#define MTILE 64
#define NTILES 782   // ceil(50000/64)
#define KPAD 136     // A smem row stride in bf16 units (272B: conflict-free ldmatrix)

typedef unsigned int uint32;

// ---------------- device scratch (no allocation allowed) ----------------
__device__ float g_h1[NN * FD];
__device__ float g_h2[NN * FD];
__device__ float g_invdeg[NN];
__device__ int   g_count[NN];
__device__ int   g_rowstart[NN];
__device__ int   g_cursor[NN];
__device__ int   g_eidx[NE];           // CSR: src ids grouped by dst
// B weights in MMA-fragment order: [layer][chunk][ks][nb][lane] -> (bh0,bh1,bl0,bl1)
__device__ uint4 g_wfrag[3 * 2 * 8 * 16 * 32];
__device__ float g_biasp[3][128];

// ---------------- PTX helpers (base-target only; NO tcgen05) ----------------
__device__ __forceinline__ uint32 smem_u32(const void* p) {
    uint32 a;
    asm("{ .reg .u64 t; cvta.to.shared.u64 t, %1; cvt.u32.u64 %0, t; }" : "=r"(a) : "l"(p));
    return a;
}

#define LDMATRIX_X4(r0, r1, r2, r3, addr) \
    asm volatile("ldmatrix.sync.aligned.m8n8.x4.shared.b16 {%0,%1,%2,%3}, [%4];" \
        : "=r"(r0), "=r"(r1), "=r"(r2), "=r"(r3) : "r"(addr))

#define MMA_BF16(d, a, b0, b1) \
    asm volatile("mma.sync.aligned.m16n8k16.row.col.f32.bf16.bf16.f32 " \
        "{%0,%1,%2,%3}, {%4,%5,%6,%7}, {%8,%9}, {%0,%1,%2,%3};" \
        : "+f"((d)[0]), "+f"((d)[1]), "+f"((d)[2]), "+f"((d)[3]) \
        : "r"((a)[0]), "r"((a)[1]), "r"((a)[2]), "r"((a)[3]), "r"(b0), "r"(b1))

// bf16 hi/lo split of a float pair -> (hi bf16x2, lo bf16x2); low half = first elem
__device__ __forceinline__ uint2 split_pair(float v0, float v1) {
    uint32 hp, lp;
    asm("cvt.rn.bf16x2.f32 %0, %1, %2;" : "=r"(hp) : "f"(v1), "f"(v0));
    float h0 = __uint_as_float(hp << 16);
    float h1 = __uint_as_float(hp & 0xFFFF0000u);
    float r0 = v0 - h0, r1 = v1 - h1;
    asm("cvt.rn.bf16x2.f32 %0, %1, %2;" : "=r"(lp) : "f"(r1), "f"(r0));
    return make_uint2(hp, lp);
}

// ---------------- CSR build ----------------

__global__ void zero_counts_kernel() {
    int i = blockIdx.x * blockDim.x + threadIdx.x;
    if (i < NN) g_count[i] = 0;
}

__global__ void hist_kernel(const int* __restrict__ dst) {
    int e = blockIdx.x * blockDim.x + threadIdx.x;
    if (e < NE) atomicAdd(&g_count[dst[e]], 1);
}

#define SCAN_T 1024
__global__ void __launch_bounds__(SCAN_T) scan_kernel() {
    __shared__ int s[SCAN_T];
    int tid = threadIdx.x;
    const int CH = (NN + SCAN_T - 1) / SCAN_T;
    int t0 = tid * CH;
    int t1 = t0 + CH; if (t1 > NN) t1 = NN;
    int sum = 0;
    for (int i = t0; i < t1; ++i) sum += g_count[i];
    s[tid] = sum;
    __syncthreads();
    for (int off = 1; off < SCAN_T; off <<= 1) {
        int v = (tid >= off) ? s[tid - off] : 0;
        __syncthreads();
        s[tid] += v;
        __syncthreads();
    }
    int run = s[tid] - sum;
    for (int i = t0; i < t1; ++i) {
        int c = g_count[i];
        g_rowstart[i] = run; run += c;
        g_invdeg[i] = 1.0f / fmaxf((float)c, 1.0f);
        g_cursor[i] = 0;
    }
}

__global__ void fill_kernel(const int* __restrict__ src, const int* __restrict__ dst) {
    int e = blockIdx.x * blockDim.x + threadIdx.x;
    if (e < NE) {
        int d = dst[e];
        int p = atomicAdd(&g_cursor[d], 1);
        g_eidx[g_rowstart[d] + p] = src[e];
    }
}

// ---------------- weight prep: fragment-order B + bias pad ----------------

__device__ __forceinline__ float get_w(int layer, int k, int n,
                                       const float* Ws0, const float* Wn0,
                                       const float* Ws1, const float* Wn1,
                                       const float* Ws2, const float* Wn2) {
    if (layer == 0) return (k < 128) ? Ws0[k * 128 + n] : Wn0[(k - 128) * 128 + n];
    if (layer == 1) return (k < 128) ? Ws1[k * 128 + n] : Wn1[(k - 128) * 128 + n];
    if (n >= 47) return 0.f;
    return (k < 128) ? Ws2[k * 47 + n] : Wn2[(k - 128) * 47 + n];
}

__device__ __forceinline__ void split1(float v, float& hi, float& lo) {
    __nv_bfloat16 hb = __float2bfloat16_rn(v);
    hi = __bfloat162float(hb);
    lo = v - hi;
}

__device__ __forceinline__ uint32 pack_bf16x2(float lo_elem, float hi_elem) {
    uint32 p;
    asm("cvt.rn.bf16x2.f32 %0, %1, %2;" : "=r"(p) : "f"(hi_elem), "f"(lo_elem));
    return p;
}

__global__ void prep_frag_kernel(const float* __restrict__ Ws0, const float* __restrict__ Wn0, const float* __restrict__ b0,
                                 const float* __restrict__ Ws1, const float* __restrict__ Wn1, const float* __restrict__ b1,
                                 const float* __restrict__ Ws2, const float* __restrict__ Wn2, const float* __restrict__ b2) {
    int i = blockIdx.x * blockDim.x + threadIdx.x;   // 0 .. 24575
    if (i < 3 * 2 * 8 * 16 * 32) {
        int lane = i & 31;
        int nb   = (i >> 5) & 15;
        int ks   = (i >> 9) & 7;
        int chunk = (i >> 12) & 1;
        int layer = i >> 13;

        int n  = nb * 8 + (lane >> 2);
        int bq = (lane & 3) * 2;
        int kb = chunk * 128 + ks * 16;

        float h0, l0, h1, l1, h2, l2, h3, l3;
        split1(get_w(layer, kb + bq,     n, Ws0, Wn0, Ws1, Wn1, Ws2, Wn2), h0, l0);
        split1(get_w(layer, kb + bq + 1, n, Ws0, Wn0, Ws1, Wn1, Ws2, Wn2), h1, l1);
        split1(get_w(layer, kb + bq + 8, n, Ws0, Wn0, Ws1, Wn1, Ws2, Wn2), h2, l2);
        split1(get_w(layer, kb + bq + 9, n, Ws0, Wn0, Ws1, Wn1, Ws2, Wn2), h3, l3);

        uint4 f;
        f.x = pack_bf16x2(h0, h1);   // bh0
        f.y = pack_bf16x2(h2, h3);   // bh1
        f.z = pack_bf16x2(l0, l1);   // bl0
        f.w = pack_bf16x2(l2, l3);   // bl1
        g_wfrag[i] = f;
    }
    if (i < 3 * 128) {
        int l = i >> 7, j = i & 127;
        float bv = 0.f;
        if (l == 0) bv = b0[j];
        else if (l == 1) bv = b1[j];
        else if (j < 47) bv = b2[j];
        g_biasp[l][j] = bv;
    }
}

// ---------------- fused gather + HMMA bf16-split dual GEMM ----------------
// Per 64-row tile:
//   phase 1: warp-local CSR gather (mean neigh) -> bf16 hi/lo SMEM -> MMA chunk1 (Wn)
//   phase 2: coalesced load of h -> bf16 hi/lo SMEM -> MMA chunk0 (Ws)
// B fragments: one coalesced LDG.128 per (ks, nt) from g_wfrag.
// Block: 8 warps, 2(M) x 4(N); warp tile 32x32; mma m16n8k16.
// smem = 2 * 64 * KPAD * 2 = 34816 (< 48KB, no opt-in).

__global__ void __launch_bounds__(256)
gemm_kernel(const float* __restrict__ h, int layer,
            float* __restrict__ out, int fout, int do_relu)
{
    extern __shared__ unsigned short smem[];
    unsigned short* s_ahi = smem;                 // [64][KPAD]
    unsigned short* s_alo = smem + MTILE * KPAD;

    const int tid = threadIdx.x;
    const int wid = tid >> 5;
    const int lane = tid & 31;
    const int warp_m = wid & 1;     // rows 32*warp_m .. +31
    const int warp_n = wid >> 1;    // cols 32*warp_n .. +31
    const int row0 = blockIdx.x * MTILE;

    const uint32 sa_hi = smem_u32(s_ahi);
    const uint32 sa_lo = smem_u32(s_alo);

    // ldmatrix lane addressing for 16x16 A tiles
    const int lm_l = lane & 7;
    const int lm_g = lane >> 3;
    const int lm_row = ((lm_g & 1) << 3) + lm_l;   // +0/+8 within tile
    const int lm_kof = (lm_g & 2) << 2;            // 0 or 8

    // layer-2 n-block activity (skip fragments/MMAs entirely past fout)
    bool nt_act[4];
#pragma unroll
    for (int nt = 0; nt < 4; ++nt)
        nt_act[nt] = (warp_n * 32 + nt * 8) < fout;

    float acc[2][4][4];
#pragma unroll
    for (int mt = 0; mt < 2; ++mt)
#pragma unroll
        for (int nt = 0; nt < 4; ++nt)
#pragma unroll
            for (int c = 0; c < 4; ++c) acc[mt][nt][c] = 0.f;

    // ================= phase 1: gather (mean neigh) -> SMEM =================
    // Warp wid owns tile rows wid*8 .. wid*8+7; lane owns feats lane*4 .. +3.
    {
#pragma unroll
        for (int rr = 0; rr < 8; ++rr) {
            int r = wid * 8 + rr;
            int node = row0 + r;
            float4 acc4 = make_float4(0.f, 0.f, 0.f, 0.f);
            float inv = 1.f;
            if (node < NN) {
                int start = 0, len = 0;
                if (lane == 0) {
                    start = g_rowstart[node];
                    len   = g_count[node];
                }
                start = __shfl_sync(0xFFFFFFFFu, start, 0);
                len   = __shfl_sync(0xFFFFFFFFu, len, 0);
                inv   = g_invdeg[node];
                int e = 0;
                for (; e + 4 <= len; e += 4) {
                    int s0 = g_eidx[start + e];
                    int s1 = g_eidx[start + e + 1];
                    int s2 = g_eidx[start + e + 2];
                    int s3 = g_eidx[start + e + 3];
                    float4 v0 = *(const float4*)(h + (size_t)s0 * FD + lane * 4);
                    float4 v1 = *(const float4*)(h + (size_t)s1 * FD + lane * 4);
                    float4 v2 = *(const float4*)(h + (size_t)s2 * FD + lane * 4);
                    float4 v3 = *(const float4*)(h + (size_t)s3 * FD + lane * 4);
                    acc4.x += v0.x + v1.x + v2.x + v3.x;
                    acc4.y += v0.y + v1.y + v2.y + v3.y;
                    acc4.z += v0.z + v1.z + v2.z + v3.z;
                    acc4.w += v0.w + v1.w + v2.w + v3.w;
                }
                for (; e < len; ++e) {
                    int s0 = g_eidx[start + e];
                    float4 v0 = *(const float4*)(h + (size_t)s0 * FD + lane * 4);
                    acc4.x += v0.x; acc4.y += v0.y; acc4.z += v0.z; acc4.w += v0.w;
                }
            }
            acc4.x *= inv; acc4.y *= inv; acc4.z *= inv; acc4.w *= inv;
            uint2 p01 = split_pair(acc4.x, acc4.y);
            uint2 p23 = split_pair(acc4.z, acc4.w);
            uint32* ph = (uint32*)(s_ahi + r * KPAD + lane * 4);
            ph[0] = p01.x; ph[1] = p23.x;
            uint32* pl = (uint32*)(s_alo + r * KPAD + lane * 4);
            pl[0] = p01.y; pl[1] = p23.y;
        }
    }
    __syncthreads();

    // ================= MMA over both chunks =================
    // pass 0: chunk1 (neigh) with SMEM holding hn; pass 1: chunk0 (self) with h.
#pragma unroll
    for (int phase = 0; phase < 2; ++phase) {
        const int chunk = 1 - phase;       // neigh first, then self
        const uint4* __restrict__ wfrag =
            g_wfrag + ((size_t)(layer * 2 + chunk) << 12);

#pragma unroll
        for (int ks = 0; ks < 8; ++ks) {
            const int k0 = ks * 16;
            uint32 ah[2][4], al[2][4];
#pragma unroll
            for (int mt = 0; mt < 2; ++mt) {
                int m = warp_m * 32 + mt * 16 + lm_row;
                uint32 off = (uint32)((m * KPAD + k0 + lm_kof) * 2);
                LDMATRIX_X4(ah[mt][0], ah[mt][1], ah[mt][2], ah[mt][3], sa_hi + off);
                LDMATRIX_X4(al[mt][0], al[mt][1], al[mt][2], al[mt][3], sa_lo + off);
            }
            uint4 bf[4];
#pragma unroll
            for (int nt = 0; nt < 4; ++nt) {
                if (nt_act[nt]) {
                    int nb = warp_n * 4 + nt;
                    bf[nt] = __ldg(&wfrag[((ks * 16 + nb) << 5) + lane]);
                }
            }
#pragma unroll
            for (int nt = 0; nt < 4; ++nt) {
                if (nt_act[nt]) {
#pragma unroll
                    for (int mt = 0; mt < 2; ++mt) {
                        MMA_BF16(acc[mt][nt], ah[mt], bf[nt].x, bf[nt].y);   // hi*hi
                        MMA_BF16(acc[mt][nt], al[mt], bf[nt].x, bf[nt].y);   // lo*hi
                        MMA_BF16(acc[mt][nt], ah[mt], bf[nt].z, bf[nt].w);   // hi*lo
                    }
                }
            }
        }

        if (phase == 0) {
            // refill SMEM with self features h (coalesced)
            __syncthreads();
#pragma unroll
            for (int it = 0; it < 8; ++it) {
                int id = tid + it * 256;       // 0..2047
                int r = id >> 5;               // row in tile (0..63)
                int q = id & 31;               // k-quad
                int row = row0 + r;
                float4 v = make_float4(0.f, 0.f, 0.f, 0.f);
                if (row < NN) v = *(const float4*)(h + (size_t)row * FD + q * 4);
                uint2 p01 = split_pair(v.x, v.y);
                uint2 p23 = split_pair(v.z, v.w);
                uint32* ph = (uint32*)(s_ahi + r * KPAD + q * 4);
                ph[0] = p01.x; ph[1] = p23.x;
                uint32* pl = (uint32*)(s_alo + r * KPAD + q * 4);
                pl[0] = p01.y; pl[1] = p23.y;
            }
            __syncthreads();
        }
    }

    // ================= epilogue: bias + relu + store =================
    const float* bias = g_biasp[layer];
#pragma unroll
    for (int mt = 0; mt < 2; ++mt) {
        int r_a = row0 + warp_m * 32 + mt * 16 + (lane >> 2);
        int r_b = r_a + 8;
#pragma unroll
        for (int nt = 0; nt < 4; ++nt) {
            if (!nt_act[nt]) continue;
            int j0 = warp_n * 32 + nt * 8 + (lane & 3) * 2;
            float b0v = bias[j0], b1v = bias[j0 + 1];
            float v0 = acc[mt][nt][0] + b0v;
            float v1 = acc[mt][nt][1] + b1v;
            float v2 = acc[mt][nt][2] + b0v;
            float v3 = acc[mt][nt][3] + b1v;
            if (do_relu) {
                v0 = fmaxf(v0, 0.f); v1 = fmaxf(v1, 0.f);
                v2 = fmaxf(v2, 0.f); v3 = fmaxf(v3, 0.f);
            }
            if (r_a < NN) {
                if (j0 < fout)     out[(size_t)r_a * fout + j0]     = v0;
                if (j0 + 1 < fout) out[(size_t)r_a * fout + j0 + 1] = v1;
            }
            if (r_b < NN) {
                if (j0 < fout)     out[(size_t)r_b * fout + j0]     = v2;
                if (j0 + 1 < fout) out[(size_t)r_b * fout + j0 + 1] = v3;
            }
        }
    }
}

// ---------------- launch ----------------

extern "C" void kernel_launch(void* const* d_in, const int* in_sizes, int n_in,
                              void* d_out, int out_size) {
    const float* x   = (const float*)d_in[0];
    const int*   src = (const int*)d_in[1];
    const int*   dst = (const int*)d_in[2];
    const float* Ws0 = (const float*)d_in[3];
    const float* Wn0 = (const float*)d_in[4];
    const float* b0  = (const float*)d_in[5];
    const float* Ws1 = (const float*)d_in[6];
    const float* Wn1 = (const float*)d_in[7];
    const float* b1  = (const float*)d_in[8];
    const float* Ws2 = (const float*)d_in[9];
    const float* Wn2 = (const float*)d_in[10];
    const float* b2  = (const float*)d_in[11];
    float* out = (float*)d_out;

    float *h1, *h2;
    cudaGetSymbolAddress((void**)&h1, g_h1);
    cudaGetSymbolAddress((void**)&h2, g_h2);

    const int smem_bytes = 2 * MTILE * KPAD * 2;   // 34816 < 48KB

    const int ZB = 256;
    const int node_grid   = (NN + ZB - 1) / ZB;
    const int edge_grid   = (NE + ZB - 1) / ZB;
    const int prep_grid   = (3 * 2 * 8 * 16 * 32 + ZB - 1) / ZB;

    // CSR build + weight prep
    zero_counts_kernel<<<node_grid, ZB>>>();
    hist_kernel<<<edge_grid, ZB>>>(dst);
    scan_kernel<<<1, SCAN_T>>>();
    fill_kernel<<<edge_grid, ZB>>>(src, dst);
    prep_frag_kernel<<<prep_grid, ZB>>>(Ws0, Wn0, b0, Ws1, Wn1, b1, Ws2, Wn2, b2);

    // fused gather+GEMM per layer
    gemm_kernel<<<NTILES, 256, smem_bytes>>>(x,  0, h1, 128, 1);
    gemm_kernel<<<NTILES, 256, smem_bytes>>>(h1, 1, h2, 128, 1);
    gemm_kernel<<<NTILES, 256, smem_bytes>>>(h2, 2, out, 47, 0);
}